// round 2
// baseline (speedup 1.0000x reference)
#include <cuda_runtime.h>
#include <cstdint>

// Problem constants (fixed by the dataset)
static constexpr int NN = 50000;
static constexpr int EE = 800000;
static constexpr int DD = 128;   // input/hidden dim
static constexpr int CC = 40;    // output classes

// ---------------- scratch (static __device__, no allocation) ----------------
__device__ float g_deg[NN];
__device__ float g_dinv[NN];
__device__ float g_hs[(size_t)NN * DD];    // pre-scaled features (x@W)*dinv[row]
__device__ float g_acc[(size_t)NN * DD];   // scatter accumulator (init = g_hs -> self loop)
__device__ float g_h[(size_t)NN * DD];     // layer activation
__device__ float g_hs3[(size_t)NN * CC];
__device__ float g_acc3[(size_t)NN * CC];

// ---------------- degree / norm ----------------
__global__ void deg_init_kernel() {
    int i = blockIdx.x * blockDim.x + threadIdx.x;
    if (i < NN) g_deg[i] = 1.0f;   // self loop
}

__global__ void deg_count_kernel(const int* __restrict__ ei) {
    int e = blockIdx.x * blockDim.x + threadIdx.x;
    if (e < EE) atomicAdd(&g_deg[ei[EE + e]], 1.0f);
}

__global__ void dinv_kernel() {
    int i = blockIdx.x * blockDim.x + threadIdx.x;
    if (i < NN) g_dinv[i] = rsqrtf(g_deg[i]);   // deg >= 1 always
}

// ---------------- GEMM: [N,128] @ [128,128], epilogue scales by dinv[row]
// and writes BOTH g_hs and g_acc (acc init covers the self-loop term).
// BM=64 BN=128 BK=16, TM=4 TN=4, 512 threads.
__global__ __launch_bounds__(512) void gemm128_kernel(
    const float* __restrict__ X, const float* __restrict__ W, int nrows) {
    __shared__ float Xs[64][17];     // +1 pad
    __shared__ float Ws[16][128];
    int tx = threadIdx.x;            // 0..31  (cols /4)
    int ty = threadIdx.y;            // 0..15  (rows /4)
    int tid = ty * 32 + tx;
    int row0 = blockIdx.x * 64;

    float c[4][4];
    #pragma unroll
    for (int i = 0; i < 4; i++)
        #pragma unroll
        for (int j = 0; j < 4; j++) c[i][j] = 0.0f;

    for (int kt = 0; kt < 128; kt += 16) {
        if (tid < 256) {
            int r  = tid >> 2;          // 0..63
            int kc = (tid & 3) * 4;     // 0,4,8,12
            float4 v = make_float4(0.f, 0.f, 0.f, 0.f);
            int grow = row0 + r;
            if (grow < nrows)
                v = *(const float4*)&X[(size_t)grow * 128 + kt + kc];
            Xs[r][kc + 0] = v.x; Xs[r][kc + 1] = v.y;
            Xs[r][kc + 2] = v.z; Xs[r][kc + 3] = v.w;
        }
        {
            int k  = tid >> 5;          // 0..15
            int c4 = (tid & 31) * 4;    // 0..124
            *(float4*)&Ws[k][c4] = *(const float4*)&W[(size_t)(kt + k) * 128 + c4];
        }
        __syncthreads();
        #pragma unroll
        for (int k = 0; k < 16; k++) {
            float a0 = Xs[ty * 4 + 0][k];
            float a1 = Xs[ty * 4 + 1][k];
            float a2 = Xs[ty * 4 + 2][k];
            float a3 = Xs[ty * 4 + 3][k];
            float4 b = *(const float4*)&Ws[k][tx * 4];
            c[0][0] += a0 * b.x; c[0][1] += a0 * b.y; c[0][2] += a0 * b.z; c[0][3] += a0 * b.w;
            c[1][0] += a1 * b.x; c[1][1] += a1 * b.y; c[1][2] += a1 * b.z; c[1][3] += a1 * b.w;
            c[2][0] += a2 * b.x; c[2][1] += a2 * b.y; c[2][2] += a2 * b.z; c[2][3] += a2 * b.w;
            c[3][0] += a3 * b.x; c[3][1] += a3 * b.y; c[3][2] += a3 * b.z; c[3][3] += a3 * b.w;
        }
        __syncthreads();
    }

    #pragma unroll
    for (int i = 0; i < 4; i++) {
        int r = row0 + ty * 4 + i;
        if (r < nrows) {
            float s = g_dinv[r];
            float4 v = make_float4(c[i][0] * s, c[i][1] * s, c[i][2] * s, c[i][3] * s);
            *(float4*)&g_hs [(size_t)r * 128 + tx * 4] = v;
            *(float4*)&g_acc[(size_t)r * 128 + tx * 4] = v;
        }
    }
}

// ---------------- edge scatter, 128 features: one warp per edge ----------------
__global__ __launch_bounds__(256) void scatter128_kernel(const int* __restrict__ ei) {
    int warp = (blockIdx.x * blockDim.x + threadIdx.x) >> 5;
    int lane = threadIdx.x & 31;
    if (warp >= EE) return;
    int src = ei[warp];
    int dst = ei[EE + warp];
    float4 v = *(const float4*)&g_hs[(size_t)src * 128 + lane * 4];
    float* p = &g_acc[(size_t)dst * 128 + lane * 4];
    asm volatile("red.global.add.v4.f32 [%0], {%1,%2,%3,%4};"
                 :: "l"(p), "f"(v.x), "f"(v.y), "f"(v.z), "f"(v.w) : "memory");
}

// ---------------- finalize: h = relu(dinv[row]*acc + b) ----------------
__global__ void finalize_relu_kernel(const float* __restrict__ b) {
    int i = blockIdx.x * blockDim.x + threadIdx.x;
    if (i >= NN * DD) return;
    int r = i >> 7;
    int col = i & 127;
    float v = g_acc[i] * g_dinv[r] + b[col];
    g_h[i] = fmaxf(v, 0.0f);
}

// ---------------- GEMM: [N,128] @ [128,40], same pre-scale epilogue ----------------
// 32 rows/block, threads (20,8): tx -> col pair, ty+8i -> rows.
__global__ __launch_bounds__(160) void gemm40_kernel(const float* __restrict__ W, int nrows) {
    __shared__ float Hs[32][128];
    __shared__ float Ws[128][40];
    int tx = threadIdx.x;           // 0..19
    int ty = threadIdx.y;           // 0..7
    int tid = ty * 20 + tx;         // 0..159
    int row0 = blockIdx.x * 32;

    for (int i = tid; i < 32 * 32; i += 160) {      // 1024 float4 of Hs
        int r  = i >> 5;
        int cc = (i & 31) * 4;
        float4 v = make_float4(0.f, 0.f, 0.f, 0.f);
        if (row0 + r < nrows)
            v = *(const float4*)&g_h[(size_t)(row0 + r) * 128 + cc];
        *(float4*)&Hs[r][cc] = v;
    }
    for (int i = tid; i < 1280; i += 160) {         // 5120 floats of W3
        *(float4*)&(((float*)Ws)[i * 4]) = *(const float4*)&W[i * 4];
    }
    __syncthreads();

    float a0[4] = {0, 0, 0, 0}, a1[4] = {0, 0, 0, 0};
    #pragma unroll 8
    for (int k = 0; k < 128; k++) {
        float2 w = *(const float2*)&Ws[k][tx * 2];
        #pragma unroll
        for (int i = 0; i < 4; i++) {
            float a = Hs[ty + 8 * i][k];
            a0[i] += a * w.x;
            a1[i] += a * w.y;
        }
    }

    #pragma unroll
    for (int i = 0; i < 4; i++) {
        int r = row0 + ty + 8 * i;
        if (r < nrows) {
            float s = g_dinv[r];
            float2 v = make_float2(a0[i] * s, a1[i] * s);
            *(float2*)&g_hs3 [(size_t)r * 40 + tx * 2] = v;
            *(float2*)&g_acc3[(size_t)r * 40 + tx * 2] = v;
        }
    }
}

// ---------------- edge scatter, 40 features: 10 threads per edge ----------------
__global__ __launch_bounds__(256) void scatter40_kernel(const int* __restrict__ ei) {
    long gid = (long)blockIdx.x * blockDim.x + threadIdx.x;
    int e = (int)(gid / 10);
    int part = (int)(gid % 10);
    if (e >= EE) return;
    int src = ei[e];
    int dst = ei[EE + e];
    float4 v = *(const float4*)&g_hs3[(size_t)src * 40 + part * 4];
    float* p = &g_acc3[(size_t)dst * 40 + part * 4];
    asm volatile("red.global.add.v4.f32 [%0], {%1,%2,%3,%4};"
                 :: "l"(p), "f"(v.x), "f"(v.y), "f"(v.z), "f"(v.w) : "memory");
}

// ---------------- finalize layer 3: out = dinv*acc + b (no relu) ----------------
__global__ void finalize3_kernel(const float* __restrict__ b, float* __restrict__ out) {
    int i = blockIdx.x * blockDim.x + threadIdx.x;
    if (i >= NN * CC) return;
    int r = i / 40;
    int col = i - r * 40;
    out[i] = g_acc3[i] * g_dinv[r] + b[col];
}

// ---------------- launch ----------------
extern "C" void kernel_launch(void* const* d_in, const int* in_sizes, int n_in,
                              void* d_out, int out_size) {
    const float* x  = (const float*)d_in[0];
    const int*   ei = (const int*)  d_in[1];
    const float* W1 = (const float*)d_in[2];
    const float* b1 = (const float*)d_in[3];
    const float* W2 = (const float*)d_in[4];
    const float* b2 = (const float*)d_in[5];
    const float* W3 = (const float*)d_in[6];
    const float* b3 = (const float*)d_in[7];
    float* out = (float*)d_out;

    // Device address of the g_h activation buffer (host-side symbol lookup is
    // NOT a valid device pointer — on GB300 ATS it silently reads host zeros).
    float* p_h = nullptr;
    cudaGetSymbolAddress((void**)&p_h, g_h);

    // norms
    deg_init_kernel<<<(NN + 255) / 256, 256>>>();
    deg_count_kernel<<<(EE + 255) / 256, 256>>>(ei);
    dinv_kernel<<<(NN + 255) / 256, 256>>>();

    dim3 gthr(32, 16);
    int gblk = (NN + 63) / 64;
    int sblk128 = (int)(((long)EE * 32 + 255) / 256);
    int fblk = (NN * DD + 255) / 256;

    // layer 1
    gemm128_kernel<<<gblk, gthr>>>(x, W1, NN);
    scatter128_kernel<<<sblk128, 256>>>(ei);
    finalize_relu_kernel<<<fblk, 256>>>(b1);

    // layer 2
    gemm128_kernel<<<gblk, gthr>>>(p_h, W2, NN);
    scatter128_kernel<<<sblk128, 256>>>(ei);
    finalize_relu_kernel<<<fblk, 256>>>(b2);

    // layer 3
    gemm40_kernel<<<(NN + 31) / 32, dim3(20, 8)>>>(W3, NN);
    int sblk40 = (int)(((long)EE * 10 + 255) / 256);
    scatter40_kernel<<<sblk40, 256>>>(ei);
    finalize3_kernel<<<(NN * CC + 255) / 256, 256>>>(b3, out);
}

// round 4
// speedup vs baseline: 1.5541x; 1.5541x over previous
#include <cuda_runtime.h>
#include <cstdint>

static constexpr int NN = 50000;
static constexpr int EE = 800000;
static constexpr int DD = 128;
static constexpr int CC = 40;

// ---------------- scratch (static __device__, no allocation) ----------------
__device__ int   g_count[NN];
__device__ int   g_off[NN + 1];
__device__ int   g_cursor[NN];
__device__ int   g_csr[EE];                 // src node per CSR slot (sorted by dst)
__device__ float g_dinv[NN];
__device__ float g_hs[(size_t)NN * DD];     // pre-scaled features (x@W)*dinv[row]
__device__ float g_h[(size_t)NN * DD];      // layer activation
__device__ float g_hs3[(size_t)NN * CC];

// ---------------- CSR build ----------------
__global__ void zero_count_kernel() {
    int i = blockIdx.x * blockDim.x + threadIdx.x;
    if (i < NN) g_count[i] = 0;
}

__global__ void hist_kernel(const int* __restrict__ ei) {
    int e = blockIdx.x * blockDim.x + threadIdx.x;
    if (e < EE) atomicAdd(&g_count[ei[EE + e]], 1);
}

// single-block scan over 50k counts (shfl-based, 2 barriers per 1024 chunk)
__global__ __launch_bounds__(1024) void scan_kernel() {
    __shared__ int wsum[32];
    __shared__ int carry_s;
    int tid = threadIdx.x;
    int lane = tid & 31;
    int wid = tid >> 5;
    if (tid == 0) carry_s = 0;
    __syncthreads();

    for (int base = 0; base < NN; base += 1024) {
        int i = base + tid;
        int orig = (i < NN) ? g_count[i] : 0;
        int v = orig;
        // warp inclusive scan
        #pragma unroll
        for (int off = 1; off < 32; off <<= 1) {
            int t = __shfl_up_sync(0xFFFFFFFFu, v, off);
            if (lane >= off) v += t;
        }
        if (lane == 31) wsum[wid] = v;
        __syncthreads();
        if (wid == 0) {
            int w = wsum[lane];
            #pragma unroll
            for (int off = 1; off < 32; off <<= 1) {
                int t = __shfl_up_sync(0xFFFFFFFFu, w, off);
                if (lane >= off) w += t;
            }
            wsum[lane] = w;
        }
        __syncthreads();
        int woff = (wid > 0) ? wsum[wid - 1] : 0;
        int incl = v + woff;
        int total = wsum[31];
        int c = carry_s;
        if (i < NN) {
            int excl = c + incl - orig;
            g_off[i] = excl;
            g_cursor[i] = excl;
        }
        __syncthreads();
        if (tid == 0) carry_s = c + total;
        __syncthreads();
    }
    if (tid == 0) g_off[NN] = carry_s;
}

__global__ void dinv_kernel() {
    int i = blockIdx.x * blockDim.x + threadIdx.x;
    if (i < NN) g_dinv[i] = rsqrtf((float)(g_count[i] + 1));  // +1 self loop
}

__global__ void fill_kernel(const int* __restrict__ ei) {
    int e = blockIdx.x * blockDim.x + threadIdx.x;
    if (e >= EE) return;
    int src = ei[e];
    int dst = ei[EE + e];
    int pos = atomicAdd(&g_cursor[dst], 1);
    g_csr[pos] = src;
}

// ---------------- GEMM [N,128]@[128,128] -> g_hs (scaled by dinv[row]) ----------------
// BM=128 BN=128 BK=8, TM=8 TN=8 (split 64-halves), 256 threads.
__global__ __launch_bounds__(256) void gemm128_v2(
    const float* __restrict__ X, const float* __restrict__ W) {
    __shared__ float As[8][132];
    __shared__ float Bs[8][128];
    int tid = threadIdx.x;
    int tx = tid & 15;
    int ty = tid >> 4;
    int row0 = blockIdx.x * 128;

    float c[8][8];
    #pragma unroll
    for (int i = 0; i < 8; i++)
        #pragma unroll
        for (int j = 0; j < 8; j++) c[i][j] = 0.0f;

    int lrow = tid >> 1;
    int lkc  = (tid & 1) * 4;
    int wr = tid >> 5;
    int wc = (tid & 31) * 4;

    for (int kt = 0; kt < 128; kt += 8) {
        float4 xv = make_float4(0.f, 0.f, 0.f, 0.f);
        int gr = row0 + lrow;
        if (gr < NN) xv = *(const float4*)&X[(size_t)gr * 128 + kt + lkc];
        As[lkc + 0][lrow] = xv.x;
        As[lkc + 1][lrow] = xv.y;
        As[lkc + 2][lrow] = xv.z;
        As[lkc + 3][lrow] = xv.w;
        *(float4*)&Bs[wr][wc] = *(const float4*)&W[(size_t)(kt + wr) * 128 + wc];
        __syncthreads();
        #pragma unroll
        for (int k = 0; k < 8; k++) {
            float a[8], b[8];
            *(float4*)&a[0] = *(const float4*)&As[k][ty * 4];
            *(float4*)&a[4] = *(const float4*)&As[k][64 + ty * 4];
            *(float4*)&b[0] = *(const float4*)&Bs[k][tx * 4];
            *(float4*)&b[4] = *(const float4*)&Bs[k][64 + tx * 4];
            #pragma unroll
            for (int i = 0; i < 8; i++)
                #pragma unroll
                for (int j = 0; j < 8; j++)
                    c[i][j] += a[i] * b[j];
        }
        __syncthreads();
    }

    #pragma unroll
    for (int i = 0; i < 8; i++) {
        int r = row0 + ((i < 4) ? (ty * 4 + i) : (64 + ty * 4 + (i - 4)));
        if (r < NN) {
            float s = g_dinv[r];
            float4 v0 = make_float4(c[i][0] * s, c[i][1] * s, c[i][2] * s, c[i][3] * s);
            float4 v1 = make_float4(c[i][4] * s, c[i][5] * s, c[i][6] * s, c[i][7] * s);
            *(float4*)&g_hs[(size_t)r * 128 + tx * 4] = v0;
            *(float4*)&g_hs[(size_t)r * 128 + 64 + tx * 4] = v1;
        }
    }
}

// ---------------- aggregation, 128 features: warp per node, CSR gather ----------------
__global__ __launch_bounds__(256) void agg128_kernel(const float* __restrict__ bias,
                                                     int do_relu) {
    int warp = (blockIdx.x * blockDim.x + threadIdx.x) >> 5;
    int lane = threadIdx.x & 31;
    if (warp >= NN) return;
    int node = warp;

    const float4* hs4 = (const float4*)g_hs;
    size_t self = (size_t)node * 32 + lane;
    float4 acc = hs4[self];                     // self-loop term

    int p = g_off[node];
    int end = g_off[node + 1];
    for (; p + 1 < end; p += 2) {
        int s0 = __ldg(&g_csr[p]);
        int s1 = __ldg(&g_csr[p + 1]);
        float4 v0 = hs4[(size_t)s0 * 32 + lane];
        float4 v1 = hs4[(size_t)s1 * 32 + lane];
        acc.x += v0.x; acc.y += v0.y; acc.z += v0.z; acc.w += v0.w;
        acc.x += v1.x; acc.y += v1.y; acc.z += v1.z; acc.w += v1.w;
    }
    if (p < end) {
        int s0 = __ldg(&g_csr[p]);
        float4 v0 = hs4[(size_t)s0 * 32 + lane];
        acc.x += v0.x; acc.y += v0.y; acc.z += v0.z; acc.w += v0.w;
    }

    float dv = g_dinv[node];
    float4 bb = *(const float4*)&bias[lane * 4];
    float4 r;
    r.x = acc.x * dv + bb.x;
    r.y = acc.y * dv + bb.y;
    r.z = acc.z * dv + bb.z;
    r.w = acc.w * dv + bb.w;
    if (do_relu) {
        r.x = fmaxf(r.x, 0.f); r.y = fmaxf(r.y, 0.f);
        r.z = fmaxf(r.z, 0.f); r.w = fmaxf(r.w, 0.f);
    }
    ((float4*)g_h)[self] = r;
}

// ---------------- GEMM [N,128]@[128,40] -> g_hs3 (scaled) ----------------
__global__ __launch_bounds__(160) void gemm40_kernel(const float* __restrict__ W) {
    __shared__ float Hs[32][128];
    __shared__ float Ws[128][40];
    int tx = threadIdx.x;           // 0..19
    int ty = threadIdx.y;           // 0..7
    int tid = ty * 20 + tx;
    int row0 = blockIdx.x * 32;

    for (int i = tid; i < 32 * 32; i += 160) {
        int r  = i >> 5;
        int cc = (i & 31) * 4;
        float4 v = make_float4(0.f, 0.f, 0.f, 0.f);
        if (row0 + r < NN)
            v = *(const float4*)&g_h[(size_t)(row0 + r) * 128 + cc];
        *(float4*)&Hs[r][cc] = v;
    }
    for (int i = tid; i < 1280; i += 160) {
        *(float4*)&(((float*)Ws)[i * 4]) = *(const float4*)&W[i * 4];
    }
    __syncthreads();

    float a0[4] = {0, 0, 0, 0}, a1[4] = {0, 0, 0, 0};
    #pragma unroll 8
    for (int k = 0; k < 128; k++) {
        float2 w = *(const float2*)&Ws[k][tx * 2];
        #pragma unroll
        for (int i = 0; i < 4; i++) {
            float a = Hs[ty + 8 * i][k];
            a0[i] += a * w.x;
            a1[i] += a * w.y;
        }
    }

    #pragma unroll
    for (int i = 0; i < 4; i++) {
        int r = row0 + ty + 8 * i;
        if (r < NN) {
            float s = g_dinv[r];
            float2 v = make_float2(a0[i] * s, a1[i] * s);
            *(float2*)&g_hs3[(size_t)r * 40 + tx * 2] = v;
        }
    }
}

// ---------------- aggregation, 40 features: warp per node, lanes 0..19 ----------------
__global__ __launch_bounds__(256) void agg40_kernel(const float* __restrict__ bias,
                                                    float* __restrict__ out) {
    int warp = (blockIdx.x * blockDim.x + threadIdx.x) >> 5;
    int lane = threadIdx.x & 31;
    if (warp >= NN || lane >= 20) return;
    int node = warp;

    float2 acc = *(const float2*)&g_hs3[(size_t)node * 40 + lane * 2];

    int p = g_off[node];
    int end = g_off[node + 1];
    for (; p + 1 < end; p += 2) {
        int s0 = __ldg(&g_csr[p]);
        int s1 = __ldg(&g_csr[p + 1]);
        float2 v0 = *(const float2*)&g_hs3[(size_t)s0 * 40 + lane * 2];
        float2 v1 = *(const float2*)&g_hs3[(size_t)s1 * 40 + lane * 2];
        acc.x += v0.x + v1.x;
        acc.y += v0.y + v1.y;
    }
    if (p < end) {
        int s0 = __ldg(&g_csr[p]);
        float2 v0 = *(const float2*)&g_hs3[(size_t)s0 * 40 + lane * 2];
        acc.x += v0.x;
        acc.y += v0.y;
    }

    float dv = g_dinv[node];
    float2 bb = *(const float2*)&bias[lane * 2];
    float2 r = make_float2(acc.x * dv + bb.x, acc.y * dv + bb.y);
    *(float2*)&out[(size_t)node * 40 + lane * 2] = r;
}

// ---------------- launch ----------------
extern "C" void kernel_launch(void* const* d_in, const int* in_sizes, int n_in,
                              void* d_out, int out_size) {
    const float* x  = (const float*)d_in[0];
    const int*   ei = (const int*)  d_in[1];
    const float* W1 = (const float*)d_in[2];
    const float* b1 = (const float*)d_in[3];
    const float* W2 = (const float*)d_in[4];
    const float* b2 = (const float*)d_in[5];
    const float* W3 = (const float*)d_in[6];
    const float* b3 = (const float*)d_in[7];
    float* out = (float*)d_out;

    float* p_h = nullptr;
    cudaGetSymbolAddress((void**)&p_h, g_h);

    // CSR + norms
    zero_count_kernel<<<(NN + 255) / 256, 256>>>();
    hist_kernel<<<(EE + 255) / 256, 256>>>(ei);
    scan_kernel<<<1, 1024>>>();
    dinv_kernel<<<(NN + 255) / 256, 256>>>();
    fill_kernel<<<(EE + 255) / 256, 256>>>(ei);

    int gblk = (NN + 127) / 128;              // 391
    int ablk = (int)(((long)NN * 32 + 255) / 256);   // 6250

    // layer 1
    gemm128_v2<<<gblk, 256>>>(x, W1);
    agg128_kernel<<<ablk, 256>>>(b1, 1);
    // layer 2
    gemm128_v2<<<gblk, 256>>>(p_h, W2);
    agg128_kernel<<<ablk, 256>>>(b2, 1);
    // layer 3
    gemm40_kernel<<<(NN + 31) / 32, dim3(20, 8)>>>(W3);
    agg40_kernel<<<ablk, 256>>>(b3, out);
}